// round 4
// baseline (speedup 1.0000x reference)
#include <cuda_runtime.h>
#include <cuda_fp16.h>

#define NUSER 100000
#define NITEM 50000
#define NEDGE 2000000
#define DIM   64
#define NLAYERS 3

// ---------------- scratch (device globals) ----------------
__device__ __half g_pu[NUSER * DIM];   // pre-scaled user operand (d_u^-1/2 * user_e)
__device__ __half g_pi[NITEM * DIM];   // pre-scaled item operand (d_i^-1/2 * item_e)
__device__ __half g_au[NUSER * DIM];   // phase-A out, user rows (d_u^-1 * R(pi))
__device__ __half g_ai[NITEM * DIM];   // phase-A out, item rows (d_i^-1 * RT(pu))
__device__ int    g_cnt_u[NUSER];
__device__ int    g_cnt_i[NITEM];
__device__ int    g_rowptr_u[NUSER + 1];
__device__ int    g_rowptr_i[NITEM + 1];
__device__ int    g_cur_u[NUSER];
__device__ int    g_cur_i[NITEM];
__device__ int    g_cols_u[NEDGE];
__device__ int    g_cols_i[NEDGE];
__device__ float  g_nu_inv[NUSER];
__device__ float  g_nu_is [NUSER];
__device__ float  g_ni_inv[NITEM];
__device__ float  g_ni_is [NITEM];

// ---------------- helpers ----------------
__device__ __forceinline__ uint4 pack8h(const float* f) {
    __half2 a = __floats2half2_rn(f[0], f[1]);
    __half2 b = __floats2half2_rn(f[2], f[3]);
    __half2 c = __floats2half2_rn(f[4], f[5]);
    __half2 d = __floats2half2_rn(f[6], f[7]);
    uint4 r;
    r.x = *reinterpret_cast<unsigned*>(&a);
    r.y = *reinterpret_cast<unsigned*>(&b);
    r.z = *reinterpret_cast<unsigned*>(&c);
    r.w = *reinterpret_cast<unsigned*>(&d);
    return r;
}

__device__ __forceinline__ void addv(float acc[8], uint4 v) {
    __half2 h0 = *reinterpret_cast<__half2*>(&v.x);
    __half2 h1 = *reinterpret_cast<__half2*>(&v.y);
    __half2 h2 = *reinterpret_cast<__half2*>(&v.z);
    __half2 h3 = *reinterpret_cast<__half2*>(&v.w);
    float2 f0 = __half22float2(h0);
    float2 f1 = __half22float2(h1);
    float2 f2 = __half22float2(h2);
    float2 f3 = __half22float2(h3);
    acc[0] += f0.x; acc[1] += f0.y; acc[2] += f1.x; acc[3] += f1.y;
    acc[4] += f2.x; acc[5] += f2.y; acc[6] += f3.x; acc[7] += f3.y;
}

// gather-add over one CSR row: 8 lanes per row, 16B (8 halves) per lane.
__device__ __forceinline__ void gather_row(const uint4* __restrict__ src,
                                           const int*   __restrict__ cols,
                                           int beg, int end, int c, unsigned qmask,
                                           float acc[8]) {
    for (int base = beg; base < end; base += 8) {
        int myi = base + c;
        int mycol = (myi < end) ? __ldg(cols + myi) : 0;
        int cnt = end - base;
        if (cnt >= 8) {
            #pragma unroll
            for (int j = 0; j < 8; ++j) {
                int col = __shfl_sync(qmask, mycol, j, 8);
                addv(acc, __ldg(src + col * 8 + c));
            }
        } else {
            for (int j = 0; j < cnt; ++j) {
                int col = __shfl_sync(qmask, mycol, j, 8);
                addv(acc, __ldg(src + col * 8 + c));
            }
        }
    }
}

// ---------------- CSR build ----------------
__global__ void hist_degrees(const int* __restrict__ u_idx,
                             const int* __restrict__ i_idx,
                             int* __restrict__ cnt_u, int* __restrict__ cnt_i) {
    int t = blockIdx.x * blockDim.x + threadIdx.x;
    if (t >= NEDGE) return;
    atomicAdd(cnt_u + __ldg(u_idx + t), 1);
    atomicAdd(cnt_i + __ldg(i_idx + t), 1);
}

// One kernel, 2 blocks of 1024: block 0 = users, block 1 = items.
// Per-thread serial chunk sum -> block scan -> write rowptr/cur/norms.
__global__ void __launch_bounds__(1024)
fused_scan(const int* __restrict__ cnt_u, const int* __restrict__ cnt_i,
           int* __restrict__ rp_u, int* __restrict__ rp_i,
           int* __restrict__ cur_u, int* __restrict__ cur_i,
           float* __restrict__ nu_inv, float* __restrict__ nu_is,
           float* __restrict__ ni_inv, float* __restrict__ ni_is) {
    const bool users = (blockIdx.x == 0);
    const int n = users ? NUSER : NITEM;
    const int* __restrict__ cnt = users ? cnt_u : cnt_i;
    int* __restrict__ rp  = users ? rp_u  : rp_i;
    int* __restrict__ cur = users ? cur_u : cur_i;
    float* __restrict__ inv = users ? nu_inv : ni_inv;
    float* __restrict__ isq = users ? nu_is  : ni_is;

    const int per = (n + 1023) / 1024;
    int beg = threadIdx.x * per;
    int end = min(n, beg + per);

    int s = 0;
    for (int e = beg; e < end; ++e) s += __ldg(cnt + e);

    __shared__ int sh[1024];
    sh[threadIdx.x] = s;
    __syncthreads();
    for (int off = 1; off < 1024; off <<= 1) {
        int t = (threadIdx.x >= off) ? sh[threadIdx.x - off] : 0;
        __syncthreads();
        sh[threadIdx.x] += t;
        __syncthreads();
    }
    int run = sh[threadIdx.x] - s;  // exclusive prefix

    for (int e = beg; e < end; ++e) {
        int c = __ldg(cnt + e);
        rp[e]  = run;
        cur[e] = run;
        float d = c ? (float)c : 1.0f;
        inv[e] = 1.0f / d;
        isq[e] = rsqrtf(d);
        run += c;
    }
    if (threadIdx.x == 0) rp[n] = NEDGE;
}

__global__ void fill_csr(const int* __restrict__ u_idx, const int* __restrict__ i_idx,
                         int* __restrict__ cur_u, int* __restrict__ cur_i,
                         int* __restrict__ cols_u, int* __restrict__ cols_i) {
    int e = blockIdx.x * blockDim.x + threadIdx.x;
    if (e >= NEDGE) return;
    int u = __ldg(u_idx + e);
    int i = __ldg(i_idx + e);
    cols_u[atomicAdd(cur_u + u, 1)] = i;
    cols_i[atomicAdd(cur_i + i, 1)] = u;
}

// ---------------- prescale: P = d^-1/2 * emb  (fp32 -> fp16) ----------------
__global__ void prescale(const float4* __restrict__ ue, const float4* __restrict__ ie,
                         const float* __restrict__ nu_is, const float* __restrict__ ni_is,
                         uint4* __restrict__ pu, uint4* __restrict__ pi) {
    int t = blockIdx.x * blockDim.x + threadIdx.x;
    if (t >= (NUSER + NITEM) * 8) return;
    const float4* src; const float* sc; uint4* dst; int tt;
    if (t < NUSER * 8) { src = ue; sc = nu_is; dst = pu; tt = t; }
    else               { src = ie; sc = ni_is; dst = pi; tt = t - NUSER * 8; }
    int r = tt >> 3, c = tt & 7;
    float s = __ldg(sc + r);
    float4 a = __ldg(src + r * 16 + c * 2);
    float4 b = __ldg(src + r * 16 + c * 2 + 1);
    float f[8] = { s*a.x, s*a.y, s*a.z, s*a.w, s*b.x, s*b.y, s*b.z, s*b.w };
    dst[tt] = pack8h(f);
}

// ---------------- phase A: ai = d_i^-1 * RT(pu);  au = d_u^-1 * R(pi) ----------------
__global__ void __launch_bounds__(256)
phaseA(const uint4* __restrict__ pu, const uint4* __restrict__ pi,
       const int* __restrict__ rp_i, const int* __restrict__ cols_i,
       const int* __restrict__ rp_u, const int* __restrict__ cols_u,
       const float* __restrict__ ni_inv, const float* __restrict__ nu_inv,
       uint4* __restrict__ ai, uint4* __restrict__ au) {
    int t = blockIdx.x * blockDim.x + threadIdx.x;
    int r = t >> 3;
    if (r >= NITEM + NUSER) return;
    int c = t & 7;
    unsigned qmask = 0xFFu << (threadIdx.x & 24);
    float acc[8] = {0,0,0,0,0,0,0,0};
    if (r < NITEM) {
        gather_row(pu, cols_i, __ldg(rp_i + r), __ldg(rp_i + r + 1), c, qmask, acc);
        float s = __ldg(ni_inv + r);
        #pragma unroll
        for (int k = 0; k < 8; ++k) acc[k] *= s;
        ai[r * 8 + c] = pack8h(acc);
    } else {
        int u = r - NITEM;
        gather_row(pi, cols_u, __ldg(rp_u + u), __ldg(rp_u + u + 1), c, qmask, acc);
        float s = __ldg(nu_inv + u);
        #pragma unroll
        for (int k = 0; k < 8; ++k) acc[k] *= s;
        au[u * 8 + c] = pack8h(acc);
    }
}

// ---------------- phase B: S_u = R(ai), S_i = RT(au); sums + next operands ----------------
__global__ void __launch_bounds__(256)
phaseB(const uint4* __restrict__ ai, const uint4* __restrict__ au,
       const int* __restrict__ rp_u, const int* __restrict__ cols_u,
       const int* __restrict__ rp_i, const int* __restrict__ cols_i,
       const float* __restrict__ nu_is, const float* __restrict__ nu_inv,
       const float* __restrict__ ni_is, const float* __restrict__ ni_inv,
       const float4* __restrict__ emb_u, const float4* __restrict__ emb_i,
       float4* __restrict__ sum_u, float4* __restrict__ sum_i,
       uint4* __restrict__ pu, uint4* __restrict__ pi,
       int layer0, int last) {
    int t = blockIdx.x * blockDim.x + threadIdx.x;
    int r = t >> 3;
    if (r >= NITEM + NUSER) return;
    int c = t & 7;
    unsigned qmask = 0xFFu << (threadIdx.x & 24);
    const float k = 1.0f / (NLAYERS + 1);
    float S[8] = {0,0,0,0,0,0,0,0};

    const float* isq; const float* inv;
    const float4* emb; float4* sum; uint4* p; int row;
    if (r < NUSER) {
        gather_row(ai, cols_u, __ldg(rp_u + r), __ldg(rp_u + r + 1), c, qmask, S);
        isq = nu_is; inv = nu_inv; emb = emb_u; sum = sum_u; p = pu; row = r;
    } else {
        row = r - NUSER;
        gather_row(au, cols_i, __ldg(rp_i + row), __ldg(rp_i + row + 1), c, qmask, S);
        isq = ni_is; inv = ni_inv; emb = emb_i; sum = sum_i; p = pi;
    }
    int i4 = row * 16 + c * 2;
    float sis = __ldg(isq + row);
    float4 b0 = layer0 ? __ldg(emb + i4)     : sum[i4];
    float4 b1 = layer0 ? __ldg(emb + i4 + 1) : sum[i4 + 1];
    float4 n0, n1;
    n0.x = b0.x + sis * S[0]; n0.y = b0.y + sis * S[1];
    n0.z = b0.z + sis * S[2]; n0.w = b0.w + sis * S[3];
    n1.x = b1.x + sis * S[4]; n1.y = b1.y + sis * S[5];
    n1.z = b1.z + sis * S[6]; n1.w = b1.w + sis * S[7];
    if (last) {
        n0.x *= k; n0.y *= k; n0.z *= k; n0.w *= k;
        n1.x *= k; n1.y *= k; n1.z *= k; n1.w *= k;
    }
    sum[i4]     = n0;
    sum[i4 + 1] = n1;
    if (!last) {
        float si = __ldg(inv + row);
        float f[8];
        #pragma unroll
        for (int j = 0; j < 8; ++j) f[j] = si * S[j];
        p[row * 8 + c] = pack8h(f);
    }
}

// ---------------- launch ----------------
extern "C" void kernel_launch(void* const* d_in, const int* in_sizes, int n_in,
                              void* d_out, int out_size) {
    const float* user_emb = (const float*)d_in[0];
    const float* item_emb = (const float*)d_in[1];
    const int*   u_idx    = (const int*)d_in[2];
    const int*   i_idx    = (const int*)d_in[3];
    float* out = (float*)d_out;
    float* sum_u = out;
    float* sum_i = out + NUSER * DIM;

    __half *p_pu, *p_pi, *p_au, *p_ai;
    float *p_nu_inv, *p_nu_is, *p_ni_inv, *p_ni_is;
    int *p_cnt_u, *p_cnt_i, *p_rp_u, *p_rp_i, *p_cur_u, *p_cur_i, *p_cols_u, *p_cols_i;
    cudaGetSymbolAddress((void**)&p_pu, g_pu);
    cudaGetSymbolAddress((void**)&p_pi, g_pi);
    cudaGetSymbolAddress((void**)&p_au, g_au);
    cudaGetSymbolAddress((void**)&p_ai, g_ai);
    cudaGetSymbolAddress((void**)&p_nu_inv, g_nu_inv);
    cudaGetSymbolAddress((void**)&p_nu_is,  g_nu_is);
    cudaGetSymbolAddress((void**)&p_ni_inv, g_ni_inv);
    cudaGetSymbolAddress((void**)&p_ni_is,  g_ni_is);
    cudaGetSymbolAddress((void**)&p_cnt_u,  g_cnt_u);
    cudaGetSymbolAddress((void**)&p_cnt_i,  g_cnt_i);
    cudaGetSymbolAddress((void**)&p_rp_u,   g_rowptr_u);
    cudaGetSymbolAddress((void**)&p_rp_i,   g_rowptr_i);
    cudaGetSymbolAddress((void**)&p_cur_u,  g_cur_u);
    cudaGetSymbolAddress((void**)&p_cur_i,  g_cur_i);
    cudaGetSymbolAddress((void**)&p_cols_u, g_cols_u);
    cudaGetSymbolAddress((void**)&p_cols_i, g_cols_i);

    const int TB = 256;
    const int EDGE_BLKS = (NEDGE + TB - 1) / TB;
    const int ALL_BLKS  = ((NUSER + NITEM) * 8 + TB - 1) / TB;

    // ---- CSR build + norms ----
    cudaMemsetAsync(p_cnt_u, 0, NUSER * sizeof(int), 0);
    cudaMemsetAsync(p_cnt_i, 0, NITEM * sizeof(int), 0);
    hist_degrees<<<EDGE_BLKS, TB>>>(u_idx, i_idx, p_cnt_u, p_cnt_i);
    fused_scan<<<2, 1024>>>(p_cnt_u, p_cnt_i, p_rp_u, p_rp_i, p_cur_u, p_cur_i,
                            p_nu_inv, p_nu_is, p_ni_inv, p_ni_is);
    fill_csr<<<EDGE_BLKS, TB>>>(u_idx, i_idx, p_cur_u, p_cur_i, p_cols_u, p_cols_i);

    // ---- initial pre-scaled operands ----
    prescale<<<ALL_BLKS, TB>>>((const float4*)user_emb, (const float4*)item_emb,
                               p_nu_is, p_ni_is, (uint4*)p_pu, (uint4*)p_pi);

    // ---- layers ----
    for (int layer = 0; layer < NLAYERS; ++layer) {
        phaseA<<<ALL_BLKS, TB>>>((const uint4*)p_pu, (const uint4*)p_pi,
                                 p_rp_i, p_cols_i, p_rp_u, p_cols_u,
                                 p_ni_inv, p_nu_inv, (uint4*)p_ai, (uint4*)p_au);
        phaseB<<<ALL_BLKS, TB>>>((const uint4*)p_ai, (const uint4*)p_au,
                                 p_rp_u, p_cols_u, p_rp_i, p_cols_i,
                                 p_nu_is, p_nu_inv, p_ni_is, p_ni_inv,
                                 (const float4*)user_emb, (const float4*)item_emb,
                                 (float4*)sum_u, (float4*)sum_i,
                                 (uint4*)p_pu, (uint4*)p_pi,
                                 layer == 0 ? 1 : 0, layer == NLAYERS - 1 ? 1 : 0);
    }
}